// round 16
// baseline (speedup 1.0000x reference)
#include <cuda_runtime.h>
#include <cuda_bf16.h>
#include <cstdint>

// ---------------- problem constants ----------------
#define WSZ 14
#define NTOK 196
#define NH 12
#define HD 64
#define CDIM 768
#define BATCH 8
#define IMG 64
#define NWIN_AX 5
#define WIN_PER_B 25
#define BW 200
#define WHTOT 2400
#define MROWS (BW*NTOK)     // 39200
#define KDIM 768
#define QKV_N (3*CDIM)      // 2304

// ---------------- scratch (device globals; no allocations allowed) ------
__device__ __align__(16) __nv_bfloat16 g_qh[(size_t)WHTOT*NTOK*HD];
__device__ __align__(16) __nv_bfloat16 g_ql[(size_t)WHTOT*NTOK*HD];
__device__ __align__(16) __nv_bfloat16 g_kh[(size_t)WHTOT*NTOK*HD];
__device__ __align__(16) __nv_bfloat16 g_kl[(size_t)WHTOT*NTOK*HD];
__device__ __align__(16) __nv_bfloat16 g_vh[(size_t)WHTOT*NTOK*HD];
__device__ __align__(16) __nv_bfloat16 g_vl[(size_t)WHTOT*NTOK*HD];
__device__ __align__(16) __nv_bfloat16 g_a_hi[(size_t)MROWS*KDIM];
__device__ __align__(16) __nv_bfloat16 g_a_lo[(size_t)MROWS*KDIM];
__device__ __align__(16) __nv_bfloat16 g_wq_hi[(size_t)QKV_N*KDIM];
__device__ __align__(16) __nv_bfloat16 g_wq_lo[(size_t)QKV_N*KDIM];
__device__ __align__(16) __nv_bfloat16 g_wp_hi[(size_t)CDIM*KDIM];
__device__ __align__(16) __nv_bfloat16 g_wp_lo[(size_t)CDIM*KDIM];
__device__ __align__(16) __nv_bfloat16 g_ao_hi[(size_t)MROWS*CDIM];
__device__ __align__(16) __nv_bfloat16 g_ao_lo[(size_t)MROWS*CDIM];
__device__ float g_cos[NTOK*32];
__device__ float g_sin[NTOK*32];

// ---------------- helpers ----------------
__device__ __forceinline__ uint32_t smem_u32(const void* p) {
    uint32_t a;
    asm("{ .reg .u64 t; cvta.to.shared.u64 t, %1; cvt.u32.u64 %0, t; }"
        : "=r"(a) : "l"(p));
    return a;
}
__device__ __forceinline__ void cp16(uint32_t dst, const void* src) {
    asm volatile("cp.async.cg.shared.global [%0], [%1], 16;" :: "r"(dst), "l"(src));
}
__device__ __forceinline__ void ldsm_x4(uint32_t* r, uint32_t addr) {
    asm volatile("ldmatrix.sync.aligned.m8n8.x4.shared.b16 {%0,%1,%2,%3}, [%4];"
        : "=r"(r[0]), "=r"(r[1]), "=r"(r[2]), "=r"(r[3]) : "r"(addr));
}
__device__ __forceinline__ void ldsm_x4_t(uint32_t* r, uint32_t addr) {
    asm volatile("ldmatrix.sync.aligned.m8n8.x4.trans.shared.b16 {%0,%1,%2,%3}, [%4];"
        : "=r"(r[0]), "=r"(r[1]), "=r"(r[2]), "=r"(r[3]) : "r"(addr));
}
__device__ __forceinline__ void mma16816(float* c, const uint32_t* a, const uint32_t* b) {
    asm volatile(
        "mma.sync.aligned.m16n8k16.row.col.f32.bf16.bf16.f32 "
        "{%0,%1,%2,%3}, {%4,%5,%6,%7}, {%8,%9}, {%0,%1,%2,%3};"
        : "+f"(c[0]), "+f"(c[1]), "+f"(c[2]), "+f"(c[3])
        : "r"(a[0]), "r"(a[1]), "r"(a[2]), "r"(a[3]), "r"(b[0]), "r"(b[1]));
}
__device__ __forceinline__ void split2(float v, __nv_bfloat16& h, __nv_bfloat16& l) {
    h = __float2bfloat16(v);
    l = __float2bfloat16(v - __bfloat162float(h));
}
__device__ __forceinline__ uint32_t cat2(__nv_bfloat16 a, __nv_bfloat16 b) {
    __nv_bfloat162 t = __halves2bfloat162(a, b);
    return *reinterpret_cast<uint32_t*>(&t);
}
__device__ __forceinline__ uint2 pack4(__nv_bfloat16 a, __nv_bfloat16 b,
                                       __nv_bfloat16 c, __nv_bfloat16 d) {
    uint2 r; r.x = cat2(a, b); r.y = cat2(c, d); return r;
}
__device__ __forceinline__ float2 bf2f2(uint32_t u) {
    __nv_bfloat162 b = *reinterpret_cast<__nv_bfloat162*>(&u);
    return __bfloat1622float2(b);
}
__device__ __forceinline__ void split_pair(float a, float b,
                                           uint32_t& hi, uint32_t& lo) {
    __nv_bfloat16 ha, la, hb, lb;
    split2(a, ha, la); split2(b, hb, lb);
    hi = cat2(ha, hb); lo = cat2(la, lb);
}

// ---------------- rope cos/sin table ----------------
__global__ void rope_table_kernel() {
    int n = blockIdx.x;
    int j = threadIdx.x;
    float tx = (float)(n % WSZ);
    float ty = (float)(n / WSZ);
    int f = (j < 16) ? j : j - 16;
    float coord = (j < 16) ? tx : ty;
    float freq = expf(-((float)(4 * f) / 64.0f) * 9.210340371976184f);
    float ang = coord * freq;
    g_cos[n * 32 + j] = cosf(ang);
    g_sin[n * 32 + j] = sinf(ang);
}

// ---------------- conversion: x -> window-permuted bf16 hi/lo -----------
__global__ __launch_bounds__(256) void convert_x_kernel(const float* __restrict__ x) {
    int g = blockIdx.x * 256 + threadIdx.x;
    if (g >= MROWS * (KDIM / 4)) return;
    int m = g / (KDIM / 4);
    int c4 = (g % (KDIM / 4)) * 4;
    int w = m / NTOK, n = m % NTOK;
    int b = w / WIN_PER_B, wr = w % WIN_PER_B;
    int wy = wr / NWIN_AX, wx = wr % NWIN_AX;
    int hp = wy * WSZ + n / WSZ;
    int wp = wx * WSZ + n % WSZ;
    float4 v = make_float4(0.f, 0.f, 0.f, 0.f);
    if (hp < IMG && wp < IMG)
        v = *(const float4*)(x + (((size_t)b * IMG + hp) * IMG + wp) * CDIM + c4);
    __nv_bfloat16 h0, h1, h2, h3, l0, l1, l2, l3;
    split2(v.x, h0, l0); split2(v.y, h1, l1);
    split2(v.z, h2, l2); split2(v.w, h3, l3);
    size_t off = (size_t)m * KDIM + c4;
    *(uint2*)(g_a_hi + off) = pack4(h0, h1, h2, h3);
    *(uint2*)(g_a_lo + off) = pack4(l0, l1, l2, l3);
}

// ---------------- conversion: weights -> bf16 hi/lo ---------------------
__global__ __launch_bounds__(256) void convert_w_kernel(
    const float* __restrict__ qkv_w, const float* __restrict__ proj_w) {
    const int NQ = QKV_N * KDIM / 4;
    const int NP = CDIM * KDIM / 4;
    int g = blockIdx.x * 256 + threadIdx.x;
    if (g >= NQ + NP) return;
    const float* src;
    __nv_bfloat16 *dh, *dl;
    size_t off;
    if (g < NQ) { off = (size_t)g * 4; src = qkv_w + off; dh = g_wq_hi; dl = g_wq_lo; }
    else { off = (size_t)(g - NQ) * 4; src = proj_w + off; dh = g_wp_hi; dl = g_wp_lo; }
    float4 v = *(const float4*)src;
    __nv_bfloat16 h0, h1, h2, h3, l0, l1, l2, l3;
    split2(v.x, h0, l0); split2(v.y, h1, l1);
    split2(v.z, h2, l2); split2(v.w, h3, l3);
    *(uint2*)(dh + off) = pack4(h0, h1, h2, h3);
    *(uint2*)(dl + off) = pack4(l0, l1, l2, l3);
}

// ---------------- mma.sync GEMM: 3-stage ring, swizzled, early-issue ----
#define TILE_B (128*64)            // 8192
#define STAGE_B (4*TILE_B)         // 32768: Ah | Al | Wh | Wl
#define SMEM_GEMM (3*STAGE_B)      // 98304
#define NSTAGE 24                  // 768/32

template<bool QKV>
__device__ __forceinline__ void gemm_load_stage(
    uint32_t sbuf, int s, int mb, int cb, int tid,
    const __nv_bfloat16* Ah, const __nv_bfloat16* Al,
    const __nv_bfloat16* Wh, const __nv_bfloat16* Wl)
{
    int row0 = tid >> 2;
    int cw = tid & 3;
    int k0 = s * 32 + cw * 8;
    int ar0 = mb + row0;        if (ar0 >= MROWS) ar0 = MROWS - 1;
    int ar1 = mb + row0 + 64;   if (ar1 >= MROWS) ar1 = MROWS - 1;
    int sc = (cw ^ ((row0 >> 1) & 3)) * 16;
    uint32_t d0 = sbuf + row0 * 64 + sc;
    uint32_t d1 = d0 + 64 * 64;
    cp16(d0, Ah + (size_t)ar0 * KDIM + k0);
    cp16(d1, Ah + (size_t)ar1 * KDIM + k0);
    cp16(d0 + TILE_B, Al + (size_t)ar0 * KDIM + k0);
    cp16(d1 + TILE_B, Al + (size_t)ar1 * KDIM + k0);
    cp16(d0 + 2 * TILE_B, Wh + (size_t)(cb + row0) * KDIM + k0);
    cp16(d1 + 2 * TILE_B, Wh + (size_t)(cb + row0 + 64) * KDIM + k0);
    cp16(d0 + 3 * TILE_B, Wl + (size_t)(cb + row0) * KDIM + k0);
    cp16(d1 + 3 * TILE_B, Wl + (size_t)(cb + row0 + 64) * KDIM + k0);
    asm volatile("cp.async.commit_group;" ::: "memory");
}

template<bool QKV>
__global__ void __launch_bounds__(256, 2) gemm_mma_kernel(
    const float* __restrict__ bias, float* __restrict__ out)
{
    const __nv_bfloat16* __restrict__ Ah = QKV ? g_a_hi : g_ao_hi;
    const __nv_bfloat16* __restrict__ Al = QKV ? g_a_lo : g_ao_lo;
    const __nv_bfloat16* __restrict__ Wh = QKV ? g_wq_hi : g_wp_hi;
    const __nv_bfloat16* __restrict__ Wl = QKV ? g_wq_lo : g_wp_lo;

    extern __shared__ char smem_g[];
    uint32_t sb = smem_u32(smem_g);
    int tid = threadIdx.x;
    int lane = tid & 31, wid = tid >> 5;
    int wm = wid >> 2, wn = wid & 3;
    int mb = blockIdx.y * 128;
    int cb = blockIdx.x * 128;

    int gq = lane >> 2;
    int qc = lane & 3;
    int l7 = lane & 7;
    int lb = (lane >> 3) & 1;
    int lc = lane >> 4;

    uint32_t rowA = (uint32_t)(wm * 64 + l7 + lb * 8);
    uint32_t swA = (rowA >> 1) & 3;
    uint32_t rowB = (uint32_t)(wn * 32 + l7);
    uint32_t swB = (rowB >> 1) & 3;

    float acc[4][4][4];
    #pragma unroll
    for (int i = 0; i < 4; i++)
        #pragma unroll
        for (int j = 0; j < 4; j++)
            #pragma unroll
            for (int c = 0; c < 4; c++) acc[i][j][c] = 0.f;

    gemm_load_stage<QKV>(sb,           0, mb, cb, tid, Ah, Al, Wh, Wl);
    gemm_load_stage<QKV>(sb + STAGE_B, 1, mb, cb, tid, Ah, Al, Wh, Wl);

    for (int s = 0; s < NSTAGE; s++) {
        if (s < NSTAGE - 1) asm volatile("cp.async.wait_group 1;" ::: "memory");
        else                asm volatile("cp.async.wait_group 0;" ::: "memory");
        __syncthreads();
        uint32_t stg = sb + (uint32_t)(s % 3) * STAGE_B;

        // ---- kk = 0: B fragments first, then early-issue next load ----
        {
            uint32_t cA = ((uint32_t)lc ^ swA) * 16;
            uint32_t cB = ((uint32_t)lb ^ swB) * 16;
            uint32_t bbase = stg + (2 + lc) * TILE_B + rowB * 64 + cB;
            uint32_t bf[4][4];
            #pragma unroll
            for (int nt = 0; nt < 4; nt++)
                ldsm_x4(bf[nt], bbase + nt * (8 * 64));
            // early issue into the slot freed by stage s-1 (barrier above)
            if (s + 2 < NSTAGE) {
                uint32_t nb = sb + (uint32_t)((s + 2) % 3) * STAGE_B;
                gemm_load_stage<QKV>(nb, s + 2, mb, cb, tid, Ah, Al, Wh, Wl);
            }
            uint32_t abase = stg + rowA * 64 + cA;
            #pragma unroll
            for (int mt = 0; mt < 4; mt++) {
                uint32_t aa = abase + mt * (16 * 64);
                uint32_t af[4], al[4];
                ldsm_x4(af, aa);
                ldsm_x4(al, aa + TILE_B);
                #pragma unroll
                for (int nt = 0; nt < 4; nt++) mma16816(acc[mt][nt], af, &bf[nt][0]);
                #pragma unroll
                for (int nt = 0; nt < 4; nt++) mma16816(acc[mt][nt], af, &bf[nt][2]);
                #pragma unroll
                for (int nt = 0; nt < 4; nt++) mma16816(acc[mt][nt], al, &bf[nt][0]);
            }
        }
        // ---- kk = 1 ----
        {
            uint32_t cA = ((uint32_t)(lc + 2) ^ swA) * 16;
            uint32_t cB = ((uint32_t)(lb + 2) ^ swB) * 16;
            uint32_t bbase = stg + (2 + lc) * TILE_B + rowB * 64 + cB;
            uint32_t bf[4][4];
            #pragma unroll
            for (int nt = 0; nt < 4; nt++)
                ldsm_x4(bf[nt], bbase + nt * (8 * 64));
            uint32_t abase = stg + rowA * 64 + cA;
            #pragma unroll
            for (int mt = 0; mt < 4; mt++) {
                uint32_t aa = abase + mt * (16 * 64);
                uint32_t af[4], al[4];
                ldsm_x4(af, aa);
                ldsm_x4(al, aa + TILE_B);
                #pragma unroll
                for (int nt = 0; nt < 4; nt++) mma16816(acc[mt][nt], af, &bf[nt][0]);
                #pragma unroll
                for (int nt = 0; nt < 4; nt++) mma16816(acc[mt][nt], af, &bf[nt][2]);
                #pragma unroll
                for (int nt = 0; nt < 4; nt++) mma16816(acc[mt][nt], al, &bf[nt][0]);
            }
        }
    }

    // ---- epilogue ----
    int tcol = 2 * qc;
    if (QKV) {
        int which = cb / CDIM;
        __nv_bfloat16* dh = (which == 0) ? g_qh : (which == 1) ? g_kh : g_vh;
        __nv_bfloat16* dl = (which == 0) ? g_ql : (which == 1) ? g_kl : g_vl;
        int hh = ((cb % CDIM) + wn * 32) / 64;
        #pragma unroll
        for (int mt = 0; mt < 4; mt++) {
            #pragma unroll
            for (int h2 = 0; h2 < 2; h2++) {
                int m = mb + wm * 64 + mt * 16 + gq + h2 * 8;
                bool mval = m < MROWS;
                int mm = mval ? m : MROWS - 1;
                int w = mm / NTOK, n = mm % NTOK;
                size_t base = (((size_t)(w * NH + hh)) * NTOK + n) * HD;
                #pragma unroll
                for (int nt = 0; nt < 4; nt++) {
                    int col = cb + wn * 32 + nt * 8 + tcol;
                    int db = col & 63;
                    float v0 = acc[mt][nt][h2 * 2 + 0] + bias[col];
                    float v1 = acc[mt][nt][h2 * 2 + 1] + bias[col + 1];
                    if (which < 2) {
                        int j0 = db >> 1;
                        float c = g_cos[n * 32 + j0], si = g_sin[n * 32 + j0];
                        float r0 = v0 * c - v1 * si;
                        float i0 = v0 * si + v1 * c;
                        v0 = r0; v1 = i0;
                    }
                    if (mval) {
                        uint32_t hi, lo;
                        split_pair(v0, v1, hi, lo);
                        *(uint32_t*)(dh + base + db) = hi;
                        *(uint32_t*)(dl + base + db) = lo;
                    }
                }
            }
        }
    } else {
        #pragma unroll
        for (int mt = 0; mt < 4; mt++) {
            #pragma unroll
            for (int h2 = 0; h2 < 2; h2++) {
                int m = mb + wm * 64 + mt * 16 + gq + h2 * 8;
                bool mval = m < MROWS;
                int mm = mval ? m : MROWS - 1;
                int w = mm / NTOK, n = mm % NTOK;
                int b = w / WIN_PER_B, wr = w % WIN_PER_B;
                int wy = wr / NWIN_AX, wx = wr % NWIN_AX;
                int hp = wy * WSZ + n / WSZ;
                int wp = wx * WSZ + n % WSZ;
                bool pv = mval && hp < IMG && wp < IMG;
                float* op = out + (((size_t)b * IMG + hp) * IMG + wp) * CDIM;
                #pragma unroll
                for (int nt = 0; nt < 4; nt++) {
                    int col = cb + wn * 32 + nt * 8 + tcol;
                    float v0 = acc[mt][nt][h2 * 2 + 0] + bias[col];
                    float v1 = acc[mt][nt][h2 * 2 + 1] + bias[col + 1];
                    if (pv) *(float2*)(op + col) = make_float2(v0, v1);
                }
            }
        }
    }
}

// ---------------- attention via mma: 448 thr, 14 warps x 16 rows --------
// R16: 2-group staging (Q first), rel-pos tables overlap K/V flight and
// are split 2 threads per row.
#define ASTRIDE 144
#define AQH 0
#define AQL 32256
#define AKH 64512
#define AKL 94464
#define AVH 124416
#define AVL 154368
#define ARH 184320
#define ARW 196864
#define ARR 209408
#define ARRW 216320
#define ATTN_SMEM 223232
#define ATHREADS 448

__device__ __forceinline__ float pexp(float dot, int r, int col, const char* sm) {
    if (col >= NTOK) return 0.f;
    int jh = (col * 18725) >> 18;       // col / 14 for col < 208
    int jw = col - jh * 14;
    float bh = ((const float*)(sm + ARH))[r * 14 + jh];
    float bw = ((const float*)(sm + ARW))[r * 14 + jw];
    return __expf(fmaf(dot, 0.125f, bh + bw));
}

__global__ void __launch_bounds__(ATHREADS, 1) attn_mma_kernel(
    const float* __restrict__ rph, const float* __restrict__ rpw)
{
    extern __shared__ char smem_a[];
    uint32_t sb = smem_u32(smem_a);
    int wh = blockIdx.x;
    int tid = threadIdx.x;
    int lane = tid & 31, wid = tid >> 5;

    size_t src0 = (size_t)wh * NTOK * HD;
    // ---- group A: Q hi/lo + rel-pos vectors ----
    for (int i = tid; i < NTOK * 8; i += ATHREADS) {
        int row = i >> 3, c = i & 7;
        cp16(sb + AQH + row * ASTRIDE + c * 16, g_qh + src0 + row * 64 + c * 8);
        cp16(sb + AQL + row * ASTRIDE + c * 16, g_ql + src0 + row * 64 + c * 8);
    }
    for (int i = tid; i < 432; i += ATHREADS) {
        cp16(sb + ARR + i * 16, rph + i * 4);
        cp16(sb + ARRW + i * 16, rpw + i * 4);
    }
    asm volatile("cp.async.commit_group;" ::: "memory");
    // ---- group B: K/V hi/lo ----
    {
        const __nv_bfloat16* bases[4] = {
            g_kh + src0, g_kl + src0, g_vh + src0, g_vl + src0};
        const uint32_t offs[4] = {AKH, AKL, AVH, AVL};
        #pragma unroll
        for (int b = 0; b < 4; b++) {
            for (int i = tid; i < NTOK * 8; i += ATHREADS) {
                int row = i >> 3, c = i & 7;
                cp16(sb + offs[b] + row * ASTRIDE + c * 16,
                     bases[b] + row * 64 + c * 8);
            }
        }
    }
    asm volatile("cp.async.commit_group;" ::: "memory");
    // zero pads (disjoint rows; overlaps in-flight loads)
    for (int i = tid; i < 28 * 36; i += ATHREADS) {
        int r = 196 + i / 36, c = i % 36;
        *(uint32_t*)(smem_a + AQH + r * ASTRIDE + c * 4) = 0;
        *(uint32_t*)(smem_a + AQL + r * ASTRIDE + c * 4) = 0;
    }
    for (int i = tid; i < 12 * 36; i += ATHREADS) {
        int r = 196 + i / 36, c = i % 36;
        *(uint32_t*)(smem_a + AKH + r * ASTRIDE + c * 4) = 0;
        *(uint32_t*)(smem_a + AKL + r * ASTRIDE + c * 4) = 0;
        *(uint32_t*)(smem_a + AVH + r * ASTRIDE + c * 4) = 0;
        *(uint32_t*)(smem_a + AVL + r * ASTRIDE + c * 4) = 0;
    }
    asm volatile("cp.async.wait_group 1;" ::: "memory");   // Q + tables landed
    __syncthreads();

    // ---- rel-pos tables: 2 threads per row (7 kh each), overlaps K/V ----
    {
        int r = tid >> 1;
        int kh0 = (tid & 1) * 7;
        if (r < NTOK) {
            float q[64];
            const uint32_t* qh = (const uint32_t*)(smem_a + AQH + r * ASTRIDE);
            const uint32_t* ql = (const uint32_t*)(smem_a + AQL + r * ASTRIDE);
            #pragma unroll
            for (int i = 0; i < 32; i++) {
                float2 a = bf2f2(qh[i]);
                float2 b = bf2f2(ql[i]);
                q[2 * i] = a.x + b.x;
                q[2 * i + 1] = a.y + b.y;
            }
            int hi_ = r / 14, wi_ = r % 14;
            #pragma unroll
            for (int k = 0; k < 7; k++) {
                int kh = kh0 + k;
                const float4* Rh4 = (const float4*)(smem_a + ARR) + (hi_ - kh + 13) * 16;
                const float4* Rw4 = (const float4*)(smem_a + ARRW) + (wi_ - kh + 13) * 16;
                float sh = 0.f, sw = 0.f;
                #pragma unroll
                for (int i = 0; i < 16; i++) {
                    float4 rh = Rh4[i];
                    float4 rw = Rw4[i];
                    sh += q[4*i] * rh.x + q[4*i+1] * rh.y + q[4*i+2] * rh.z + q[4*i+3] * rh.w;
                    sw += q[4*i] * rw.x + q[4*i+1] * rw.y + q[4*i+2] * rw.z + q[4*i+3] * rw.w;
                }
                ((float*)(smem_a + ARH))[r * 14 + kh] = sh;
                ((float*)(smem_a + ARW))[r * 14 + kh] = sw;
            }
        } else {
            #pragma unroll
            for (int k = 0; k < 7; k++) {
                ((float*)(smem_a + ARH))[r * 14 + kh0 + k] = 0.f;
                ((float*)(smem_a + ARW))[r * 14 + kh0 + k] = 0.f;
            }
        }
    }
    asm volatile("cp.async.wait_group 0;" ::: "memory");   // K/V landed
    __syncthreads();

    // 14 compute warps, 16 query rows each
    int l7 = lane & 7;
    int lb = (lane >> 3) & 1;
    int lc = lane >> 4;
    int g = lane >> 2, qc = lane & 3;

    uint32_t qrow = sb + (uint32_t)((wid * 16 + l7 + lb * 8) * ASTRIDE + lc * 16);

    float acc[8][4];
    #pragma unroll
    for (int n8 = 0; n8 < 8; n8++)
        #pragma unroll
        for (int c = 0; c < 4; c++) acc[n8][c] = 0.f;
    float ls0 = 0.f, ls1 = 0.f;

    for (int jt = 0; jt < 13; jt++) {
        int jb = jt * 16;
        float c[2][4];
        #pragma unroll
        for (int nt = 0; nt < 2; nt++)
            #pragma unroll
            for (int q4 = 0; q4 < 4; q4++) c[nt][q4] = 0.f;

        // S = QK^T (3-term hi/lo)
        #pragma unroll
        for (int kk = 0; kk < 4; kk++) {
            uint32_t qh[4], ql[4];
            ldsm_x4(qh, qrow + AQH + kk * 32);
            ldsm_x4(ql, qrow + AQL + kk * 32);
            #pragma unroll
            for (int kt = 0; kt < 2; kt++) {
                uint32_t kb[4];
                ldsm_x4(kb, sb + AKH + (uint32_t)((jb + kt * 8 + l7) * ASTRIDE
                        + lb * 16 + kk * 32 + lc * (AKL - AKH)));
                mma16816(c[kt], qh, &kb[0]);
                mma16816(c[kt], qh, &kb[2]);
                mma16816(c[kt], ql, &kb[0]);
            }
        }

        // exp + bias; P split hi/lo in registers
        uint32_t aPh[4], aPl[4];
        {
            int r0 = wid * 16 + g;
            int r1 = r0 + 8;
            #pragma unroll
            for (int nt = 0; nt < 2; nt++) {
                int col0 = jb + nt * 8 + 2 * qc;
                float p0 = pexp(c[nt][0], r0, col0, smem_a);
                float p1 = pexp(c[nt][1], r0, col0 + 1, smem_a);
                float p2 = pexp(c[nt][2], r1, col0, smem_a);
                float p3 = pexp(c[nt][3], r1, col0 + 1, smem_a);
                ls0 += p0 + p1;
                ls1 += p2 + p3;
                split_pair(p0, p1, aPh[nt * 2 + 0], aPl[nt * 2 + 0]);
                split_pair(p2, p3, aPh[nt * 2 + 1], aPl[nt * 2 + 1]);
            }
        }

        // PV: 3-term (Ph*Vh + Ph*Vl + Pl*Vh)
        #pragma unroll
        for (int hb = 0; hb < 4; hb++) {
            uint32_t bh[4], bl[4];
            uint32_t va = sb + (uint32_t)((jb + l7 + lb * 8) * ASTRIDE + hb * 32 + lc * 16);
            ldsm_x4_t(bh, va + AVH);
            ldsm_x4_t(bl, va + AVL);
            mma16816(acc[hb * 2 + 0], aPh, &bh[0]);
            mma16816(acc[hb * 2 + 0], aPh, &bl[0]);
            mma16816(acc[hb * 2 + 0], aPl, &bh[0]);
            mma16816(acc[hb * 2 + 1], aPh, &bh[2]);
            mma16816(acc[hb * 2 + 1], aPh, &bl[2]);
            mma16816(acc[hb * 2 + 1], aPl, &bh[2]);
        }
    }

    // ---- normalize + store (bf16 hi/lo for proj GEMM) ----
    int w = wh / NH, h = wh % NH;
    {
        float l0 = ls0;
        l0 += __shfl_xor_sync(0xffffffff, l0, 1);
        l0 += __shfl_xor_sync(0xffffffff, l0, 2);
        float l1 = ls1;
        l1 += __shfl_xor_sync(0xffffffff, l1, 1);
        l1 += __shfl_xor_sync(0xffffffff, l1, 2);
        float i0 = 1.f / l0, i1 = 1.f / l1;
        int r0 = wid * 16 + g;
        int r1 = r0 + 8;
        size_t b0 = ((size_t)(w * NTOK + r0)) * CDIM + h * HD;
        size_t b1 = ((size_t)(w * NTOK + r1)) * CDIM + h * HD;
        #pragma unroll
        for (int n8 = 0; n8 < 8; n8++) {
            int colo = n8 * 8 + 2 * qc;
            if (r0 < NTOK) {
                uint32_t hi, lo;
                split_pair(acc[n8][0] * i0, acc[n8][1] * i0, hi, lo);
                *(uint32_t*)(g_ao_hi + b0 + colo) = hi;
                *(uint32_t*)(g_ao_lo + b0 + colo) = lo;
            }
            if (r1 < NTOK) {
                uint32_t hi, lo;
                split_pair(acc[n8][2] * i1, acc[n8][3] * i1, hi, lo);
                *(uint32_t*)(g_ao_hi + b1 + colo) = hi;
                *(uint32_t*)(g_ao_lo + b1 + colo) = lo;
            }
        }
    }
}

// ---------------- launch ----------------
extern "C" void kernel_launch(void* const* d_in, const int* in_sizes, int n_in,
                              void* d_out, int out_size) {
    const float* x      = (const float*)d_in[0];
    const float* qkv_w  = (const float*)d_in[1];
    const float* qkv_b  = (const float*)d_in[2];
    const float* proj_w = (const float*)d_in[3];
    const float* proj_b = (const float*)d_in[4];
    const float* rph    = (const float*)d_in[5];
    const float* rpw    = (const float*)d_in[6];
    float* out = (float*)d_out;

    cudaFuncSetAttribute(attn_mma_kernel,
                         cudaFuncAttributeMaxDynamicSharedMemorySize, ATTN_SMEM);
    cudaFuncSetAttribute(gemm_mma_kernel<true>,
                         cudaFuncAttributeMaxDynamicSharedMemorySize, SMEM_GEMM);
    cudaFuncSetAttribute(gemm_mma_kernel<false>,
                         cudaFuncAttributeMaxDynamicSharedMemorySize, SMEM_GEMM);

    rope_table_kernel<<<NTOK, 32>>>();
    convert_w_kernel<<<(QKV_N*KDIM/4 + CDIM*KDIM/4 + 255) / 256, 256>>>(qkv_w, proj_w);
    convert_x_kernel<<<(MROWS*(KDIM/4) + 255) / 256, 256>>>(x);
    gemm_mma_kernel<true><<<dim3(18, 307), 256, SMEM_GEMM>>>(qkv_b, nullptr);
    attn_mma_kernel<<<WHTOT, ATHREADS, ATTN_SMEM>>>(rph, rpw);
    gemm_mma_kernel<false><<<dim3(6, 307), 256, SMEM_GEMM>>>(proj_b, out);
}

// round 17
// speedup vs baseline: 1.0143x; 1.0143x over previous
#include <cuda_runtime.h>
#include <cuda_bf16.h>
#include <cstdint>

// ---------------- problem constants ----------------
#define WSZ 14
#define NTOK 196
#define NH 12
#define HD 64
#define CDIM 768
#define BATCH 8
#define IMG 64
#define NWIN_AX 5
#define WIN_PER_B 25
#define BW 200
#define WHTOT 2400
#define MROWS (BW*NTOK)     // 39200
#define KDIM 768
#define QKV_N (3*CDIM)      // 2304

// ---------------- scratch (device globals; no allocations allowed) ------
__device__ __align__(16) __nv_bfloat16 g_qh[(size_t)WHTOT*NTOK*HD];
__device__ __align__(16) __nv_bfloat16 g_ql[(size_t)WHTOT*NTOK*HD];
__device__ __align__(16) __nv_bfloat16 g_kh[(size_t)WHTOT*NTOK*HD];
__device__ __align__(16) __nv_bfloat16 g_kl[(size_t)WHTOT*NTOK*HD];
__device__ __align__(16) __nv_bfloat16 g_vh[(size_t)WHTOT*NTOK*HD];
__device__ __align__(16) __nv_bfloat16 g_vl[(size_t)WHTOT*NTOK*HD];
__device__ __align__(16) __nv_bfloat16 g_a_hi[(size_t)MROWS*KDIM];
__device__ __align__(16) __nv_bfloat16 g_a_lo[(size_t)MROWS*KDIM];
__device__ __align__(16) __nv_bfloat16 g_wq_hi[(size_t)QKV_N*KDIM];
__device__ __align__(16) __nv_bfloat16 g_wq_lo[(size_t)QKV_N*KDIM];
__device__ __align__(16) __nv_bfloat16 g_wp_hi[(size_t)CDIM*KDIM];
__device__ __align__(16) __nv_bfloat16 g_wp_lo[(size_t)CDIM*KDIM];
__device__ __align__(16) __nv_bfloat16 g_ao_hi[(size_t)MROWS*CDIM];
__device__ __align__(16) __nv_bfloat16 g_ao_lo[(size_t)MROWS*CDIM];
__device__ float g_cos[NTOK*32];
__device__ float g_sin[NTOK*32];

// ---------------- helpers ----------------
__device__ __forceinline__ uint32_t smem_u32(const void* p) {
    uint32_t a;
    asm("{ .reg .u64 t; cvta.to.shared.u64 t, %1; cvt.u32.u64 %0, t; }"
        : "=r"(a) : "l"(p));
    return a;
}
__device__ __forceinline__ void cp16(uint32_t dst, const void* src) {
    asm volatile("cp.async.cg.shared.global [%0], [%1], 16;" :: "r"(dst), "l"(src));
}
__device__ __forceinline__ void ldsm_x4(uint32_t* r, uint32_t addr) {
    asm volatile("ldmatrix.sync.aligned.m8n8.x4.shared.b16 {%0,%1,%2,%3}, [%4];"
        : "=r"(r[0]), "=r"(r[1]), "=r"(r[2]), "=r"(r[3]) : "r"(addr));
}
__device__ __forceinline__ void ldsm_x4_t(uint32_t* r, uint32_t addr) {
    asm volatile("ldmatrix.sync.aligned.m8n8.x4.trans.shared.b16 {%0,%1,%2,%3}, [%4];"
        : "=r"(r[0]), "=r"(r[1]), "=r"(r[2]), "=r"(r[3]) : "r"(addr));
}
__device__ __forceinline__ void mma16816(float* c, const uint32_t* a, const uint32_t* b) {
    asm volatile(
        "mma.sync.aligned.m16n8k16.row.col.f32.bf16.bf16.f32 "
        "{%0,%1,%2,%3}, {%4,%5,%6,%7}, {%8,%9}, {%0,%1,%2,%3};"
        : "+f"(c[0]), "+f"(c[1]), "+f"(c[2]), "+f"(c[3])
        : "r"(a[0]), "r"(a[1]), "r"(a[2]), "r"(a[3]), "r"(b[0]), "r"(b[1]));
}
__device__ __forceinline__ void split2(float v, __nv_bfloat16& h, __nv_bfloat16& l) {
    h = __float2bfloat16(v);
    l = __float2bfloat16(v - __bfloat162float(h));
}
__device__ __forceinline__ uint32_t cat2(__nv_bfloat16 a, __nv_bfloat16 b) {
    __nv_bfloat162 t = __halves2bfloat162(a, b);
    return *reinterpret_cast<uint32_t*>(&t);
}
__device__ __forceinline__ uint2 pack4(__nv_bfloat16 a, __nv_bfloat16 b,
                                       __nv_bfloat16 c, __nv_bfloat16 d) {
    uint2 r; r.x = cat2(a, b); r.y = cat2(c, d); return r;
}
__device__ __forceinline__ float2 bf2f2(uint32_t u) {
    __nv_bfloat162 b = *reinterpret_cast<__nv_bfloat162*>(&u);
    return __bfloat1622float2(b);
}
__device__ __forceinline__ void split_pair(float a, float b,
                                           uint32_t& hi, uint32_t& lo) {
    __nv_bfloat16 ha, la, hb, lb;
    split2(a, ha, la); split2(b, hb, lb);
    hi = cat2(ha, hb); lo = cat2(la, lb);
}

// ---------------- rope cos/sin table ----------------
__global__ void rope_table_kernel() {
    int n = blockIdx.x;
    int j = threadIdx.x;
    float tx = (float)(n % WSZ);
    float ty = (float)(n / WSZ);
    int f = (j < 16) ? j : j - 16;
    float coord = (j < 16) ? tx : ty;
    float freq = expf(-((float)(4 * f) / 64.0f) * 9.210340371976184f);
    float ang = coord * freq;
    g_cos[n * 32 + j] = cosf(ang);
    g_sin[n * 32 + j] = sinf(ang);
}

// ---------------- conversion: x -> window-permuted bf16 hi/lo -----------
__global__ __launch_bounds__(256) void convert_x_kernel(const float* __restrict__ x) {
    int g = blockIdx.x * 256 + threadIdx.x;
    if (g >= MROWS * (KDIM / 4)) return;
    int m = g / (KDIM / 4);
    int c4 = (g % (KDIM / 4)) * 4;
    int w = m / NTOK, n = m % NTOK;
    int b = w / WIN_PER_B, wr = w % WIN_PER_B;
    int wy = wr / NWIN_AX, wx = wr % NWIN_AX;
    int hp = wy * WSZ + n / WSZ;
    int wp = wx * WSZ + n % WSZ;
    float4 v = make_float4(0.f, 0.f, 0.f, 0.f);
    if (hp < IMG && wp < IMG)
        v = *(const float4*)(x + (((size_t)b * IMG + hp) * IMG + wp) * CDIM + c4);
    __nv_bfloat16 h0, h1, h2, h3, l0, l1, l2, l3;
    split2(v.x, h0, l0); split2(v.y, h1, l1);
    split2(v.z, h2, l2); split2(v.w, h3, l3);
    size_t off = (size_t)m * KDIM + c4;
    *(uint2*)(g_a_hi + off) = pack4(h0, h1, h2, h3);
    *(uint2*)(g_a_lo + off) = pack4(l0, l1, l2, l3);
}

// ---------------- conversion: weights -> bf16 hi/lo ---------------------
__global__ __launch_bounds__(256) void convert_w_kernel(
    const float* __restrict__ qkv_w, const float* __restrict__ proj_w) {
    const int NQ = QKV_N * KDIM / 4;
    const int NP = CDIM * KDIM / 4;
    int g = blockIdx.x * 256 + threadIdx.x;
    if (g >= NQ + NP) return;
    const float* src;
    __nv_bfloat16 *dh, *dl;
    size_t off;
    if (g < NQ) { off = (size_t)g * 4; src = qkv_w + off; dh = g_wq_hi; dl = g_wq_lo; }
    else { off = (size_t)(g - NQ) * 4; src = proj_w + off; dh = g_wp_hi; dl = g_wp_lo; }
    float4 v = *(const float4*)src;
    __nv_bfloat16 h0, h1, h2, h3, l0, l1, l2, l3;
    split2(v.x, h0, l0); split2(v.y, h1, l1);
    split2(v.z, h2, l2); split2(v.w, h3, l3);
    *(uint2*)(dh + off) = pack4(h0, h1, h2, h3);
    *(uint2*)(dl + off) = pack4(l0, l1, l2, l3);
}

// ---------------- mma.sync GEMM (R15-proven): 3-stage ring, swizzled ----
#define TILE_B (128*64)            // 8192
#define STAGE_B (4*TILE_B)         // 32768: Ah | Al | Wh | Wl
#define SMEM_GEMM (3*STAGE_B)      // 98304
#define NSTAGE 24                  // 768/32

template<bool QKV>
__device__ __forceinline__ void gemm_load_stage(
    uint32_t sbuf, int s, int mb, int cb, int tid,
    const __nv_bfloat16* Ah, const __nv_bfloat16* Al,
    const __nv_bfloat16* Wh, const __nv_bfloat16* Wl)
{
    int row0 = tid >> 2;
    int cw = tid & 3;
    int k0 = s * 32 + cw * 8;
    int ar0 = mb + row0;        if (ar0 >= MROWS) ar0 = MROWS - 1;
    int ar1 = mb + row0 + 64;   if (ar1 >= MROWS) ar1 = MROWS - 1;
    int sc = (cw ^ ((row0 >> 1) & 3)) * 16;
    uint32_t d0 = sbuf + row0 * 64 + sc;
    uint32_t d1 = d0 + 64 * 64;
    cp16(d0, Ah + (size_t)ar0 * KDIM + k0);
    cp16(d1, Ah + (size_t)ar1 * KDIM + k0);
    cp16(d0 + TILE_B, Al + (size_t)ar0 * KDIM + k0);
    cp16(d1 + TILE_B, Al + (size_t)ar1 * KDIM + k0);
    cp16(d0 + 2 * TILE_B, Wh + (size_t)(cb + row0) * KDIM + k0);
    cp16(d1 + 2 * TILE_B, Wh + (size_t)(cb + row0 + 64) * KDIM + k0);
    cp16(d0 + 3 * TILE_B, Wl + (size_t)(cb + row0) * KDIM + k0);
    cp16(d1 + 3 * TILE_B, Wl + (size_t)(cb + row0 + 64) * KDIM + k0);
    asm volatile("cp.async.commit_group;" ::: "memory");
}

template<bool QKV>
__global__ void __launch_bounds__(256, 2) gemm_mma_kernel(
    const float* __restrict__ bias, float* __restrict__ out)
{
    const __nv_bfloat16* __restrict__ Ah = QKV ? g_a_hi : g_ao_hi;
    const __nv_bfloat16* __restrict__ Al = QKV ? g_a_lo : g_ao_lo;
    const __nv_bfloat16* __restrict__ Wh = QKV ? g_wq_hi : g_wp_hi;
    const __nv_bfloat16* __restrict__ Wl = QKV ? g_wq_lo : g_wp_lo;

    extern __shared__ char smem_g[];
    uint32_t sb = smem_u32(smem_g);
    int tid = threadIdx.x;
    int lane = tid & 31, wid = tid >> 5;
    int wm = wid >> 2, wn = wid & 3;
    int mb = blockIdx.y * 128;
    int cb = blockIdx.x * 128;

    int gq = lane >> 2;
    int qc = lane & 3;
    int l7 = lane & 7;
    int lb = (lane >> 3) & 1;
    int lc = lane >> 4;

    uint32_t rowA = (uint32_t)(wm * 64 + l7 + lb * 8);
    uint32_t swA = (rowA >> 1) & 3;
    uint32_t rowB = (uint32_t)(wn * 32 + l7);
    uint32_t swB = (rowB >> 1) & 3;

    float acc[4][4][4];
    #pragma unroll
    for (int i = 0; i < 4; i++)
        #pragma unroll
        for (int j = 0; j < 4; j++)
            #pragma unroll
            for (int c = 0; c < 4; c++) acc[i][j][c] = 0.f;

    gemm_load_stage<QKV>(sb,           0, mb, cb, tid, Ah, Al, Wh, Wl);
    gemm_load_stage<QKV>(sb + STAGE_B, 1, mb, cb, tid, Ah, Al, Wh, Wl);

    for (int s = 0; s < NSTAGE; s++) {
        if (s < NSTAGE - 1) asm volatile("cp.async.wait_group 1;" ::: "memory");
        else                asm volatile("cp.async.wait_group 0;" ::: "memory");
        __syncthreads();
        if (s + 2 < NSTAGE) {
            uint32_t nb = sb + (uint32_t)((s + 2) % 3) * STAGE_B;
            gemm_load_stage<QKV>(nb, s + 2, mb, cb, tid, Ah, Al, Wh, Wl);
        }
        uint32_t stg = sb + (uint32_t)(s % 3) * STAGE_B;

        #pragma unroll
        for (int kk = 0; kk < 2; kk++) {
            uint32_t cA = ((uint32_t)(lc + 2 * kk) ^ swA) * 16;
            uint32_t cB = ((uint32_t)(lb + 2 * kk) ^ swB) * 16;
            uint32_t bbase = stg + (2 + lc) * TILE_B + rowB * 64 + cB;
            uint32_t bf[4][4];
            #pragma unroll
            for (int nt = 0; nt < 4; nt++)
                ldsm_x4(bf[nt], bbase + nt * (8 * 64));
            uint32_t abase = stg + rowA * 64 + cA;
            #pragma unroll
            for (int mt = 0; mt < 4; mt++) {
                uint32_t aa = abase + mt * (16 * 64);
                uint32_t af[4], al[4];
                ldsm_x4(af, aa);
                ldsm_x4(al, aa + TILE_B);
                #pragma unroll
                for (int nt = 0; nt < 4; nt++) mma16816(acc[mt][nt], af, &bf[nt][0]);
                #pragma unroll
                for (int nt = 0; nt < 4; nt++) mma16816(acc[mt][nt], af, &bf[nt][2]);
                #pragma unroll
                for (int nt = 0; nt < 4; nt++) mma16816(acc[mt][nt], al, &bf[nt][0]);
            }
        }
    }

    // ---- epilogue ----
    int tcol = 2 * qc;
    if (QKV) {
        int which = cb / CDIM;
        __nv_bfloat16* dh = (which == 0) ? g_qh : (which == 1) ? g_kh : g_vh;
        __nv_bfloat16* dl = (which == 0) ? g_ql : (which == 1) ? g_kl : g_vl;
        int hh = ((cb % CDIM) + wn * 32) / 64;
        #pragma unroll
        for (int mt = 0; mt < 4; mt++) {
            #pragma unroll
            for (int h2 = 0; h2 < 2; h2++) {
                int m = mb + wm * 64 + mt * 16 + gq + h2 * 8;
                bool mval = m < MROWS;
                int mm = mval ? m : MROWS - 1;
                int w = mm / NTOK, n = mm % NTOK;
                size_t base = (((size_t)(w * NH + hh)) * NTOK + n) * HD;
                #pragma unroll
                for (int nt = 0; nt < 4; nt++) {
                    int col = cb + wn * 32 + nt * 8 + tcol;
                    int db = col & 63;
                    float v0 = acc[mt][nt][h2 * 2 + 0] + bias[col];
                    float v1 = acc[mt][nt][h2 * 2 + 1] + bias[col + 1];
                    if (which < 2) {
                        int j0 = db >> 1;
                        float c = g_cos[n * 32 + j0], si = g_sin[n * 32 + j0];
                        float r0 = v0 * c - v1 * si;
                        float i0 = v0 * si + v1 * c;
                        v0 = r0; v1 = i0;
                    }
                    if (mval) {
                        uint32_t hi, lo;
                        split_pair(v0, v1, hi, lo);
                        *(uint32_t*)(dh + base + db) = hi;
                        *(uint32_t*)(dl + base + db) = lo;
                    }
                }
            }
        }
    } else {
        #pragma unroll
        for (int mt = 0; mt < 4; mt++) {
            #pragma unroll
            for (int h2 = 0; h2 < 2; h2++) {
                int m = mb + wm * 64 + mt * 16 + gq + h2 * 8;
                bool mval = m < MROWS;
                int mm = mval ? m : MROWS - 1;
                int w = mm / NTOK, n = mm % NTOK;
                int b = w / WIN_PER_B, wr = w % WIN_PER_B;
                int wy = wr / NWIN_AX, wx = wr % NWIN_AX;
                int hp = wy * WSZ + n / WSZ;
                int wp = wx * WSZ + n % WSZ;
                bool pv = mval && hp < IMG && wp < IMG;
                float* op = out + (((size_t)b * IMG + hp) * IMG + wp) * CDIM;
                #pragma unroll
                for (int nt = 0; nt < 4; nt++) {
                    int col = cb + wn * 32 + nt * 8 + tcol;
                    float v0 = acc[mt][nt][h2 * 2 + 0] + bias[col];
                    float v1 = acc[mt][nt][h2 * 2 + 1] + bias[col + 1];
                    if (pv) *(float2*)(op + col) = make_float2(v0, v1);
                }
            }
        }
    }
}

// ---------------- attention via mma: 448 thr, 14 warps x 16 rows --------
// R17: Q fragments hoisted out of the j-loop (j-invariant; saves ~96
// ldsm.x4/warp). Prolog keeps R16's 2-group staging + split tables.
#define ASTRIDE 144
#define AQH 0
#define AQL 32256
#define AKH 64512
#define AKL 94464
#define AVH 124416
#define AVL 154368
#define ARH 184320
#define ARW 196864
#define ARR 209408
#define ARRW 216320
#define ATTN_SMEM 223232
#define ATHREADS 448

__device__ __forceinline__ float pexp(float dot, int r, int col, const char* sm) {
    if (col >= NTOK) return 0.f;
    int jh = (col * 18725) >> 18;       // col / 14 for col < 208
    int jw = col - jh * 14;
    float bh = ((const float*)(sm + ARH))[r * 14 + jh];
    float bw = ((const float*)(sm + ARW))[r * 14 + jw];
    return __expf(fmaf(dot, 0.125f, bh + bw));
}

__global__ void __launch_bounds__(ATHREADS, 1) attn_mma_kernel(
    const float* __restrict__ rph, const float* __restrict__ rpw)
{
    extern __shared__ char smem_a[];
    uint32_t sb = smem_u32(smem_a);
    int wh = blockIdx.x;
    int tid = threadIdx.x;
    int lane = tid & 31, wid = tid >> 5;

    size_t src0 = (size_t)wh * NTOK * HD;
    // ---- group A: Q hi/lo + rel-pos vectors ----
    for (int i = tid; i < NTOK * 8; i += ATHREADS) {
        int row = i >> 3, c = i & 7;
        cp16(sb + AQH + row * ASTRIDE + c * 16, g_qh + src0 + row * 64 + c * 8);
        cp16(sb + AQL + row * ASTRIDE + c * 16, g_ql + src0 + row * 64 + c * 8);
    }
    for (int i = tid; i < 432; i += ATHREADS) {
        cp16(sb + ARR + i * 16, rph + i * 4);
        cp16(sb + ARRW + i * 16, rpw + i * 4);
    }
    asm volatile("cp.async.commit_group;" ::: "memory");
    // ---- group B: K/V hi/lo ----
    {
        const __nv_bfloat16* bases[4] = {
            g_kh + src0, g_kl + src0, g_vh + src0, g_vl + src0};
        const uint32_t offs[4] = {AKH, AKL, AVH, AVL};
        #pragma unroll
        for (int b = 0; b < 4; b++) {
            for (int i = tid; i < NTOK * 8; i += ATHREADS) {
                int row = i >> 3, c = i & 7;
                cp16(sb + offs[b] + row * ASTRIDE + c * 16,
                     bases[b] + row * 64 + c * 8);
            }
        }
    }
    asm volatile("cp.async.commit_group;" ::: "memory");
    // zero pads (disjoint rows; overlaps in-flight loads)
    for (int i = tid; i < 28 * 36; i += ATHREADS) {
        int r = 196 + i / 36, c = i % 36;
        *(uint32_t*)(smem_a + AQH + r * ASTRIDE + c * 4) = 0;
        *(uint32_t*)(smem_a + AQL + r * ASTRIDE + c * 4) = 0;
    }
    for (int i = tid; i < 12 * 36; i += ATHREADS) {
        int r = 196 + i / 36, c = i % 36;
        *(uint32_t*)(smem_a + AKH + r * ASTRIDE + c * 4) = 0;
        *(uint32_t*)(smem_a + AKL + r * ASTRIDE + c * 4) = 0;
        *(uint32_t*)(smem_a + AVH + r * ASTRIDE + c * 4) = 0;
        *(uint32_t*)(smem_a + AVL + r * ASTRIDE + c * 4) = 0;
    }
    asm volatile("cp.async.wait_group 1;" ::: "memory");   // Q + tables landed
    __syncthreads();

    // ---- rel-pos tables: 2 threads per row (7 kh each), overlaps K/V ----
    {
        int r = tid >> 1;
        int kh0 = (tid & 1) * 7;
        if (r < NTOK) {
            float q[64];
            const uint32_t* qh = (const uint32_t*)(smem_a + AQH + r * ASTRIDE);
            const uint32_t* ql = (const uint32_t*)(smem_a + AQL + r * ASTRIDE);
            #pragma unroll
            for (int i = 0; i < 32; i++) {
                float2 a = bf2f2(qh[i]);
                float2 b = bf2f2(ql[i]);
                q[2 * i] = a.x + b.x;
                q[2 * i + 1] = a.y + b.y;
            }
            int hi_ = r / 14, wi_ = r % 14;
            #pragma unroll
            for (int k = 0; k < 7; k++) {
                int kh = kh0 + k;
                const float4* Rh4 = (const float4*)(smem_a + ARR) + (hi_ - kh + 13) * 16;
                const float4* Rw4 = (const float4*)(smem_a + ARRW) + (wi_ - kh + 13) * 16;
                float sh = 0.f, sw = 0.f;
                #pragma unroll
                for (int i = 0; i < 16; i++) {
                    float4 rh = Rh4[i];
                    float4 rw = Rw4[i];
                    sh += q[4*i] * rh.x + q[4*i+1] * rh.y + q[4*i+2] * rh.z + q[4*i+3] * rh.w;
                    sw += q[4*i] * rw.x + q[4*i+1] * rw.y + q[4*i+2] * rw.z + q[4*i+3] * rw.w;
                }
                ((float*)(smem_a + ARH))[r * 14 + kh] = sh;
                ((float*)(smem_a + ARW))[r * 14 + kh] = sw;
            }
        } else {
            #pragma unroll
            for (int k = 0; k < 7; k++) {
                ((float*)(smem_a + ARH))[r * 14 + kh0 + k] = 0.f;
                ((float*)(smem_a + ARW))[r * 14 + kh0 + k] = 0.f;
            }
        }
    }
    asm volatile("cp.async.wait_group 0;" ::: "memory");   // K/V landed
    __syncthreads();

    // 14 compute warps, 16 query rows each
    int l7 = lane & 7;
    int lb = (lane >> 3) & 1;
    int lc = lane >> 4;
    int g = lane >> 2, qc = lane & 3;

    uint32_t qrow = sb + (uint32_t)((wid * 16 + l7 + lb * 8) * ASTRIDE + lc * 16);

    // ---- hoisted Q fragments (j-invariant) ----
    uint32_t qf_h[4][4], qf_l[4][4];
    #pragma unroll
    for (int kk = 0; kk < 4; kk++) {
        ldsm_x4(qf_h[kk], qrow + AQH + kk * 32);
        ldsm_x4(qf_l[kk], qrow + AQL + kk * 32);
    }

    float acc[8][4];
    #pragma unroll
    for (int n8 = 0; n8 < 8; n8++)
        #pragma unroll
        for (int c = 0; c < 4; c++) acc[n8][c] = 0.f;
    float ls0 = 0.f, ls1 = 0.f;

    for (int jt = 0; jt < 13; jt++) {
        int jb = jt * 16;
        float c[2][4];
        #pragma unroll
        for (int nt = 0; nt < 2; nt++)
            #pragma unroll
            for (int q4 = 0; q4 < 4; q4++) c[nt][q4] = 0.f;

        // S = QK^T (3-term hi/lo)
        #pragma unroll
        for (int kk = 0; kk < 4; kk++) {
            #pragma unroll
            for (int kt = 0; kt < 2; kt++) {
                uint32_t kb[4];
                ldsm_x4(kb, sb + AKH + (uint32_t)((jb + kt * 8 + l7) * ASTRIDE
                        + lb * 16 + kk * 32 + lc * (AKL - AKH)));
                mma16816(c[kt], qf_h[kk], &kb[0]);
                mma16816(c[kt], qf_h[kk], &kb[2]);
                mma16816(c[kt], qf_l[kk], &kb[0]);
            }
        }

        // exp + bias; P split hi/lo in registers
        uint32_t aPh[4], aPl[4];
        {
            int r0 = wid * 16 + g;
            int r1 = r0 + 8;
            #pragma unroll
            for (int nt = 0; nt < 2; nt++) {
                int col0 = jb + nt * 8 + 2 * qc;
                float p0 = pexp(c[nt][0], r0, col0, smem_a);
                float p1 = pexp(c[nt][1], r0, col0 + 1, smem_a);
                float p2 = pexp(c[nt][2], r1, col0, smem_a);
                float p3 = pexp(c[nt][3], r1, col0 + 1, smem_a);
                ls0 += p0 + p1;
                ls1 += p2 + p3;
                split_pair(p0, p1, aPh[nt * 2 + 0], aPl[nt * 2 + 0]);
                split_pair(p2, p3, aPh[nt * 2 + 1], aPl[nt * 2 + 1]);
            }
        }

        // PV: 3-term (Ph*Vh + Ph*Vl + Pl*Vh)
        #pragma unroll
        for (int hb = 0; hb < 4; hb++) {
            uint32_t bh[4], bl[4];
            uint32_t va = sb + (uint32_t)((jb + l7 + lb * 8) * ASTRIDE + hb * 32 + lc * 16);
            ldsm_x4_t(bh, va + AVH);
            ldsm_x4_t(bl, va + AVL);
            mma16816(acc[hb * 2 + 0], aPh, &bh[0]);
            mma16816(acc[hb * 2 + 0], aPh, &bl[0]);
            mma16816(acc[hb * 2 + 0], aPl, &bh[0]);
            mma16816(acc[hb * 2 + 1], aPh, &bh[2]);
            mma16816(acc[hb * 2 + 1], aPh, &bl[2]);
            mma16816(acc[hb * 2 + 1], aPl, &bh[2]);
        }
    }

    // ---- normalize + store (bf16 hi/lo for proj GEMM) ----
    int w = wh / NH, h = wh % NH;
    {
        float l0 = ls0;
        l0 += __shfl_xor_sync(0xffffffff, l0, 1);
        l0 += __shfl_xor_sync(0xffffffff, l0, 2);
        float l1 = ls1;
        l1 += __shfl_xor_sync(0xffffffff, l1, 1);
        l1 += __shfl_xor_sync(0xffffffff, l1, 2);
        float i0 = 1.f / l0, i1 = 1.f / l1;
        int r0 = wid * 16 + g;
        int r1 = r0 + 8;
        size_t b0 = ((size_t)(w * NTOK + r0)) * CDIM + h * HD;
        size_t b1 = ((size_t)(w * NTOK + r1)) * CDIM + h * HD;
        #pragma unroll
        for (int n8 = 0; n8 < 8; n8++) {
            int colo = n8 * 8 + 2 * qc;
            if (r0 < NTOK) {
                uint32_t hi, lo;
                split_pair(acc[n8][0] * i0, acc[n8][1] * i0, hi, lo);
                *(uint32_t*)(g_ao_hi + b0 + colo) = hi;
                *(uint32_t*)(g_ao_lo + b0 + colo) = lo;
            }
            if (r1 < NTOK) {
                uint32_t hi, lo;
                split_pair(acc[n8][2] * i1, acc[n8][3] * i1, hi, lo);
                *(uint32_t*)(g_ao_hi + b1 + colo) = hi;
                *(uint32_t*)(g_ao_lo + b1 + colo) = lo;
            }
        }
    }
}

// ---------------- launch ----------------
extern "C" void kernel_launch(void* const* d_in, const int* in_sizes, int n_in,
                              void* d_out, int out_size) {
    const float* x      = (const float*)d_in[0];
    const float* qkv_w  = (const float*)d_in[1];
    const float* qkv_b  = (const float*)d_in[2];
    const float* proj_w = (const float*)d_in[3];
    const float* proj_b = (const float*)d_in[4];
    const float* rph    = (const float*)d_in[5];
    const float* rpw    = (const float*)d_in[6];
    float* out = (float*)d_out;

    cudaFuncSetAttribute(attn_mma_kernel,
                         cudaFuncAttributeMaxDynamicSharedMemorySize, ATTN_SMEM);
    cudaFuncSetAttribute(gemm_mma_kernel<true>,
                         cudaFuncAttributeMaxDynamicSharedMemorySize, SMEM_GEMM);
    cudaFuncSetAttribute(gemm_mma_kernel<false>,
                         cudaFuncAttributeMaxDynamicSharedMemorySize, SMEM_GEMM);

    rope_table_kernel<<<NTOK, 32>>>();
    convert_w_kernel<<<(QKV_N*KDIM/4 + CDIM*KDIM/4 + 255) / 256, 256>>>(qkv_w, proj_w);
    convert_x_kernel<<<(MROWS*(KDIM/4) + 255) / 256, 256>>>(x);
    gemm_mma_kernel<true><<<dim3(18, 307), 256, SMEM_GEMM>>>(qkv_b, nullptr);
    attn_mma_kernel<<<WHTOT, ATHREADS, ATTN_SMEM>>>(rph, rpw);
    gemm_mma_kernel<false><<<dim3(6, 307), 256, SMEM_GEMM>>>(proj_b, out);
}